// round 4
// baseline (speedup 1.0000x reference)
#include <cuda_runtime.h>
#include <math.h>
#include <limits.h>

#define S_STAGES 3
#define BATCH    32
#define NPRIOR   2000
#define LANES    4
#define DFEAT    78          // 2 + 4 + 72
#define NOFF     72
#define SB       (S_STAGES * BATCH)   // 96
#define IMG_W_F  800.0f
#define IMG_W1_F 799.0f
#define NSPLIT   20
#define PPB      (NPRIOR / NSPLIT)    // 100 priors per block
#define NMATCH   (2 * SB * LANES)     // 768
#define NCLSPART 4
#define SBPART   (SB / NCLSPART)      // 24

// Scratch (device globals — no allocation allowed)
__device__ float g_cneg[2 * SB * NPRIOR];                    // 1.5 MB
__device__ float g_cpos[2 * SB * NPRIOR];                    // 1.5 MB
__device__ float g_cv[2 * SB * LANES * NSPLIT * 4];          // candidates: values
__device__ int   g_ci[2 * SB * LANES * NSPLIT * 4];          // candidates: indices
__device__ float g_cls_part[NCLSPART * 2 * NPRIOR];

// ---------------------------------------------------------------------------
// Kernel 1: streaming cost + focal terms + per-chunk top-4 candidates/column.
// grid (96, NSPLIT, 2), 256 threads, warp-per-prior.
// ---------------------------------------------------------------------------
__global__ __launch_bounds__(256) void cost_kernel(
    const float* __restrict__ predA,
    const float* __restrict__ predB,
    const float* __restrict__ gt)
{
    const int sb     = blockIdx.x;
    const int chunk  = blockIdx.y;
    const int branch = blockIdx.z;
    const int n0     = chunk * PPB;
    const float* __restrict__ pred = branch ? predB : predA;
    const int b = sb % BATCH;
    const float* prow_base = pred + (size_t)sb * NPRIOR * DFEAT;

    __shared__ float sh_geo [LANES][4];
    __shared__ float sh_goff[LANES][NOFF];
    __shared__ float sh_c[LANES][PPB];

    const int tid = threadIdx.x;
    for (int i = tid; i < LANES * DFEAT; i += 256) {
        int l = i / DFEAT, d = i % DFEAT;
        float v = gt[((size_t)b * LANES + l) * DFEAT + d];
        if (d >= 2 && d < 6) sh_geo[l][d - 2] = v;
        if (d >= 6)          sh_goff[l][d - 6] = v * (1.0f / IMG_W1_F);
    }
    __syncthreads();

    const int warp = tid >> 5, lane = tid & 31;
    const unsigned FULL = 0xffffffffu;
    const size_t bs = (size_t)branch * SB + sb;

    for (int n = n0 + warp; n < n0 + PPB; n += 8) {
        const float* p = prow_base + (size_t)n * DFEAT;
        float v0 = p[lane];
        float v1 = p[lane + 32];
        float v2 = (lane < DFEAT - 64) ? p[lane + 64] : 0.0f;

        float x0 = __shfl_sync(FULL, v0, 0);
        float x1 = __shfl_sync(FULL, v0, 1);

        float c[LANES];
        #pragma unroll
        for (int l = 0; l < LANES; l++) {
            float gg = 0.0f, oo = 0.0f;
            if (lane >= 2 && lane < 6) gg = fabsf(v0 - sh_geo[l][lane - 2]);
            if (lane >= 6)             oo += fabsf(v0 - sh_goff[l][lane - 6]);
            oo += fabsf(v1 - sh_goff[l][lane + 26]);
            if (lane < DFEAT - 64)     oo += fabsf(v2 - sh_goff[l][lane + 58]);
            c[l] = gg + oo * (1.0f / 72.0f);
        }
        #pragma unroll
        for (int off = 16; off; off >>= 1) {
            #pragma unroll
            for (int l = 0; l < LANES; l++)
                c[l] += __shfl_xor_sync(FULL, c[l], off);
        }

        float m  = fmaxf(x0, x1);
        float e0 = expf(x0 - m), e1 = expf(x1 - m);
        float denom = e0 + e1;
        float score = e1 / denom;

        if (lane < LANES)
            sh_c[lane][n - n0] = c[lane] - score;

        float lse   = m + logf(denom);
        float logp0 = x0 - lse, logp1 = x1 - lse;
        float pt0 = e0 / denom, pt1 = score;
        float om0 = 1.0f - pt0, om1 = 1.0f - pt1;
        if (lane == 4) g_cneg[bs * NPRIOR + n] = -0.1f * om0 * om0 * logp0;
        if (lane == 5) g_cpos[bs * NPRIOR + n] = -0.9f * om1 * om1 * logp1;
    }
    __syncthreads();

    // warps 0..3: top-4 (value,index) of column w, first-index tie-break
    if (warp < LANES) {
        const int w = warp;
        const size_t base = ((bs * LANES + w) * NSPLIT + chunk) * 4;
        #pragma unroll
        for (int pass = 0; pass < 4; pass++) {
            float v = INFINITY; int ii = INT_MAX;
            for (int j = lane; j < PPB; j += 32) {
                float cc = sh_c[w][j];
                int   gi = n0 + j;
                if (cc < v || (cc == v && gi < ii)) { v = cc; ii = gi; }
            }
            #pragma unroll
            for (int off = 16; off; off >>= 1) {
                float v2 = __shfl_xor_sync(FULL, v, off);
                int   i2 = __shfl_xor_sync(FULL, ii, off);
                if (v2 < v || (v2 == v && i2 < ii)) { v = v2; ii = i2; }
            }
            if (lane == 0) {
                g_cv[base + pass] = v;
                g_ci[base + pass] = ii;
                sh_c[w][ii - n0] = INFINITY;
            }
            __syncwarp(FULL);
        }
    }
}

// ---------------------------------------------------------------------------
// Kernel 2: partial cls-neg reduction over sb. grid (8, 2, NCLSPART).
// ---------------------------------------------------------------------------
__global__ __launch_bounds__(256) void cls_kernel()
{
    const int n = blockIdx.x * 256 + threadIdx.x;
    const int branch = blockIdx.y;
    const int part   = blockIdx.z;
    if (n >= NPRIOR) return;
    const float* base = g_cneg + ((size_t)branch * SB + part * SBPART) * NPRIOR + n;
    float acc = 0.0f;
    #pragma unroll
    for (int i = 0; i < SBPART; i++) acc += base[(size_t)i * NPRIOR];
    g_cls_part[((size_t)part * 2 + branch) * NPRIOR + n] = acc;
}

// ---------------------------------------------------------------------------
// Kernel 3: merge candidates + greedy + reg/iou + corrections + radix-select
//           median + final weighted sum. Single block, 1024 threads.
// ---------------------------------------------------------------------------
__global__ __launch_bounds__(1024) void final_kernel(
    const float* __restrict__ predA,
    const float* __restrict__ predB,
    const float* __restrict__ gt,
    const float* __restrict__ diff,
    float* __restrict__ out)
{
    __shared__ float instA[NPRIOR];
    __shared__ float instB[NPRIOR];
    __shared__ unsigned ukey[NPRIOR];
    __shared__ float reg_sh[NMATCH];
    __shared__ float iou_sh[NMATCH];
    __shared__ int   rows_sh[NMATCH];
    __shared__ int   hist[256];
    __shared__ float red[1024];
    __shared__ int   s_bin, s_k;

    const int tid = threadIdx.x;
    const unsigned FULL = 0xffffffffu;

    // ---- (a) greedy assignment: thread-per-(branch,sb) task ----
    if (tid < 2 * SB) {
        const int branch = tid / SB;
        const int sb     = tid % SB;
        const size_t bs  = (size_t)branch * SB + sb;
        int used[3];
        #pragma unroll
        for (int col = 0; col < LANES; col++) {
            const size_t base = (bs * LANES + col) * NSPLIT * 4;
            float best = INFINITY; int bi = INT_MAX;
            for (int j = 0; j < NSPLIT * 4; j++) {
                int i = g_ci[base + j];
                bool excl = false;
                #pragma unroll
                for (int u = 0; u < 3; u++) excl |= (u < col && i == used[u]);
                if (excl) continue;
                float v = g_cv[base + j];
                if (v < best || (v == best && i < bi)) { best = v; bi = i; }
            }
            rows_sh[bs * LANES + col] = bi;
            if (col < 3) used[col] = bi;
        }
    }

    // ---- init inst from cls partials ----
    for (int n = tid; n < NPRIOR; n += 1024) {
        float a0 = g_cls_part[0 * NPRIOR + n] + g_cls_part[2 * NPRIOR + n]
                 + g_cls_part[4 * NPRIOR + n] + g_cls_part[6 * NPRIOR + n];
        float b0 = g_cls_part[1 * NPRIOR + n] + g_cls_part[3 * NPRIOR + n]
                 + g_cls_part[5 * NPRIOR + n] + g_cls_part[7 * NPRIOR + n];
        instA[n] = a0 * (2.0f / 96.0f);   // CLS_W / (B*S)
        instB[n] = b0 * (2.0f / 96.0f);
    }
    __syncthreads();

    // ---- (b) reg + iou: warp-per-match ----
    {
        const int warp = tid >> 5, lane = tid & 31;
        for (int m = warp; m < NMATCH; m += 32) {
            const int branch = m / (SB * LANES);
            const int rem    = m % (SB * LANES);
            const int sb     = rem / LANES;
            const int l      = rem % LANES;
            const int b      = sb % BATCH;
            const int r      = rows_sh[m];
            const float* p  = (branch ? predB : predA)
                              + ((size_t)sb * NPRIOR + r) * DFEAT;
            const float* tg = gt + ((size_t)b * LANES + l) * DFEAT;

            float ovrS = 0.0f, uniS = 0.0f;
            for (int k = lane; k < NOFF; k += 32) {
                float rp = p[6 + k] * IMG_W1_F;
                float rt = tg[6 + k];
                bool invalid = (rt < 0.0f) || (rt >= IMG_W_F);
                float mn = fminf(rp, rt), mx = fmaxf(rp, rt);
                if (!invalid) {
                    ovrS += (mn - mx + 30.0f);
                    uniS += (mx - mn + 30.0f);
                }
            }
            #pragma unroll
            for (int off = 16; off; off >>= 1) {
                ovrS += __shfl_xor_sync(FULL, ovrS, off);
                uniS += __shfl_xor_sync(FULL, uniS, off);
            }
            if (lane == 0) {
                float iou = ovrS / (uniS + 1e-9f);
                iou_sh[m] = (1.0f - iou) * 0.25f;
                const float sc[4] = {71.0f, IMG_W1_F, 180.0f, 71.0f};
                float ssum = 0.0f;
                #pragma unroll
                for (int j = 0; j < 4; j++) {
                    float d  = (p[2 + j] - tg[2 + j]) * sc[j];
                    float ad = fabsf(d);
                    ssum += (ad < 1.0f) ? 0.5f * d * d : ad - 0.5f;
                }
                reg_sh[m] = ssum * 0.0625f;   // mean over 4, /L
            }
        }
    }
    __syncthreads();

    // ---- (c) corrections into inst ----
    if (tid < NMATCH) {
        const int branch = tid / (SB * LANES);
        const int rem    = tid % (SB * LANES);
        const int sb     = rem / LANES;
        const int r      = rows_sh[tid];
        const size_t idx = ((size_t)branch * SB + sb) * NPRIOR + r;
        float corr = (g_cpos[idx] - g_cneg[idx]) * (2.0f / 96.0f);
        atomicAdd(branch == 0 ? &instA[r] : &instB[r], corr);
    }
    if (tid >= 1016) {   // 8 threads: reg/iou sums + scatter at rows[-1,-1]
        const int t = tid - 1016;
        const int branch = t >> 2, l = t & 3;
        float rs = 0.0f, is = 0.0f;
        #pragma unroll 8
        for (int i = 0; i < SB; i++) {
            rs += reg_sh[(branch * SB + i) * LANES + l];
            is += iou_sh[(branch * SB + i) * LANES + l];
        }
        float add = rs * (0.5f / 96.0f) + is * (2.0f / 96.0f);
        int r = rows_sh[(branch * SB + (SB - 1)) * LANES + l];
        atomicAdd(branch == 0 ? &instA[r] : &instB[r], add);
    }
    __syncthreads();

    // ---- (d) median of (instA - instB) via radix select ----
    for (int n = tid; n < NPRIOR; n += 1024) {
        float f = instA[n] - instB[n];
        unsigned x = __float_as_uint(f);
        ukey[n] = (x & 0x80000000u) ? ~x : (x | 0x80000000u);
    }
    __syncthreads();

    float medv[2];
    #pragma unroll
    for (int which = 0; which < 2; which++) {
        int kk = 999 + which;
        unsigned prefix = 0, mask = 0;
        for (int shift = 24; shift >= 0; shift -= 8) {
            if (tid < 256) hist[tid] = 0;
            __syncthreads();
            for (int n = tid; n < NPRIOR; n += 1024) {
                unsigned u = ukey[n];
                if ((u & mask) == prefix)
                    atomicAdd(&hist[(u >> shift) & 255], 1);
            }
            __syncthreads();
            if (tid == 0) {
                int c = kk;
                int bsel = 255;
                for (int bi = 0; bi < 256; bi++) {
                    int h = hist[bi];
                    if (c < h) { bsel = bi; break; }
                    c -= h;
                }
                s_bin = bsel; s_k = c;
            }
            __syncthreads();
            prefix |= ((unsigned)s_bin) << shift;
            mask   |= 0xFFu << shift;
            kk = s_k;
            __syncthreads();
        }
        medv[which] = (prefix & 0x80000000u)
                      ? __uint_as_float(prefix ^ 0x80000000u)
                      : __uint_as_float(~prefix);
    }
    float delta = 0.5f * (medv[0] + medv[1]);

    // ---- (e) final weighted sum ----
    float acc = 0.0f;
    for (int n = tid; n < NPRIOR; n += 1024) {
        float dm = (diff[n] + diff[NPRIOR + n] + diff[2 * NPRIOR + n]) * (1.0f / 3.0f);
        acc += (1.0f - dm) * (instA[n] - 0.5f * delta)
             + dm          * (instB[n] + 0.5f * delta);
    }
    red[tid] = acc;
    __syncthreads();
    for (int off = 512; off; off >>= 1) {
        if (tid < off) red[tid] += red[tid + off];
        __syncthreads();
    }
    if (tid == 0) out[0] = red[0];
}

// ---------------------------------------------------------------------------
extern "C" void kernel_launch(void* const* d_in, const int* in_sizes, int n_in,
                              void* d_out, int out_size)
{
    const float* fir  = (const float*)d_in[0];
    const float* sec  = (const float*)d_in[1];
    const float* gt   = (const float*)d_in[2];
    const float* diff = (const float*)d_in[3];
    float* out = (float*)d_out;

    cost_kernel <<<dim3(SB, NSPLIT, 2), 256>>>(fir, sec, gt);
    cls_kernel  <<<dim3((NPRIOR + 255) / 256, 2, NCLSPART), 256>>>();
    final_kernel<<<1, 1024>>>(fir, sec, gt, diff, out);
}

// round 5
// speedup vs baseline: 1.1406x; 1.1406x over previous
#include <cuda_runtime.h>
#include <math.h>
#include <limits.h>

#define S_STAGES 3
#define BATCH    32
#define NPRIOR   2000
#define LANES    4
#define DFEAT    78          // 2 + 4 + 72
#define NOFF     72
#define SB       96
#define IMG_W_F  800.0f
#define IMG_W1_F 799.0f
#define TILE     128
#define NTILE    16          // 15 full tiles + one of 80
#define RPAD     84          // padded row stride (floats): conflict-free LDS.128
#define NCAND    (NTILE * 4) // 64 candidates per column
#define NMATCH   (2 * SB * LANES)   // 768
#define NCLSPART 4
#define SBPART   (SB / NCLSPART)

// Scratch (device globals — no allocation allowed)
__device__ float g_cneg[2 * SB * NPRIOR];
__device__ float g_cpos[2 * SB * NPRIOR];
__device__ float g_cv[2 * SB * LANES * NCAND];
__device__ int   g_ci[2 * SB * LANES * NCAND];
__device__ float g_cls_part[NCLSPART * 2 * NPRIOR];

// ---------------------------------------------------------------------------
// Kernel 1: thread-per-prior cost + focal terms + per-tile top-4 candidates.
// grid (96, NTILE, 2), 128 threads. SMEM-staged tile, no shuffles in hot loop.
// ---------------------------------------------------------------------------
__global__ __launch_bounds__(TILE) void cost_kernel(
    const float* __restrict__ predA,
    const float* __restrict__ predB,
    const float* __restrict__ gt)
{
    const int sb     = blockIdx.x;
    const int tile   = blockIdx.y;
    const int branch = blockIdx.z;
    const int n0     = tile * TILE;
    const int T      = (n0 + TILE <= NPRIOR) ? TILE : (NPRIOR - n0);
    const float* __restrict__ pred = branch ? predB : predA;
    const int b = sb % BATCH;
    const float* gbase = pred + ((size_t)sb * NPRIOR + n0) * DFEAT;
    const size_t bs = (size_t)branch * SB + sb;

    __shared__ __align__(16) float sh_pred[TILE * RPAD];   // 43008 B
    __shared__ __align__(16) float sh_goff[LANES][80];     // indexed by dim, zeros outside [6,78)
    __shared__ float sh_geo[LANES][4];
    __shared__ float sh_c[LANES][TILE];

    const int tid  = threadIdx.x;
    const int warp = tid >> 5, lane = tid & 31;
    const unsigned FULL = 0xffffffffu;

    // gt offsets (by dim index, padded with zeros) + geo dims
    for (int i = tid; i < LANES * 80; i += TILE) {
        int l = i / 80, d = i % 80;
        float v = 0.0f;
        if (d >= 6 && d < DFEAT)
            v = gt[((size_t)b * LANES + l) * DFEAT + d] * (1.0f / IMG_W1_F);
        sh_goff[l][d] = v;
    }
    if (tid < 16)
        sh_geo[tid >> 2][tid & 3] =
            gt[((size_t)b * LANES + (tid >> 2)) * DFEAT + 2 + (tid & 3)];

    // stage tile rows: warp-per-row, coalesced; zero pad dims 78,79
    for (int r = warp; r < T; r += 4) {
        const float* row = gbase + (size_t)r * DFEAT;
        float* srow = sh_pred + r * RPAD;
        srow[lane]      = row[lane];
        srow[lane + 32] = row[lane + 32];
        if (lane < 14)      srow[lane + 64] = row[lane + 64];
        else if (lane < 16) srow[lane + 64] = 0.0f;
    }
    __syncthreads();

    if (tid < T) {
        const float* rp = sh_pred + tid * RPAD;
        float4 p0 = *reinterpret_cast<const float4*>(rp);       // dims 0-3
        float4 p1 = *reinterpret_cast<const float4*>(rp + 4);   // dims 4-7

        float cg[LANES], o[LANES];
        #pragma unroll
        for (int l = 0; l < LANES; l++) {
            cg[l] = fabsf(p0.z - sh_geo[l][0]) + fabsf(p0.w - sh_geo[l][1])
                  + fabsf(p1.x - sh_geo[l][2]) + fabsf(p1.y - sh_geo[l][3]);
            o[l]  = fabsf(p1.z - sh_goff[l][6]) + fabsf(p1.w - sh_goff[l][7]);
        }
        #pragma unroll
        for (int c = 2; c < 20; c++) {                           // dims 8..79 (78,79 zero-padded)
            float4 pv = *reinterpret_cast<const float4*>(rp + 4 * c);
            #pragma unroll
            for (int l = 0; l < LANES; l++) {
                float4 gv = *reinterpret_cast<const float4*>(&sh_goff[l][4 * c]);
                o[l] += fabsf(pv.x - gv.x) + fabsf(pv.y - gv.y)
                      + fabsf(pv.z - gv.z) + fabsf(pv.w - gv.w);
            }
        }

        float x0 = p0.x, x1 = p0.y;
        float m  = fmaxf(x0, x1);
        float e0 = expf(x0 - m), e1 = expf(x1 - m);
        float denom = e0 + e1;
        float score = e1 / denom;
        #pragma unroll
        for (int l = 0; l < LANES; l++)
            sh_c[l][tid] = cg[l] + o[l] * (1.0f / 72.0f) - score;

        float lse = m + logf(denom);
        float pt0 = e0 / denom;
        float om0 = 1.0f - pt0, om1 = 1.0f - score;
        g_cneg[bs * NPRIOR + n0 + tid] = -0.1f * om0 * om0 * (x0 - lse);
        g_cpos[bs * NPRIOR + n0 + tid] = -0.9f * om1 * om1 * (x1 - lse);
    } else {
        #pragma unroll
        for (int l = 0; l < LANES; l++) sh_c[l][tid] = INFINITY;
    }
    __syncthreads();

    // warp w: top-4 (value,index) of column w within this tile, first-index tie-break
    {
        const int w = warp;
        const size_t base = ((bs * LANES + w) * NTILE + tile) * 4;
        #pragma unroll
        for (int pass = 0; pass < 4; pass++) {
            float v = INFINITY; int li = INT_MAX;
            #pragma unroll
            for (int j0 = 0; j0 < TILE; j0 += 32) {
                int j = j0 + lane;
                float cc = sh_c[w][j];
                if (cc < v || (cc == v && j < li)) { v = cc; li = j; }
            }
            #pragma unroll
            for (int off = 16; off; off >>= 1) {
                float v2 = __shfl_xor_sync(FULL, v, off);
                int   i2 = __shfl_xor_sync(FULL, li, off);
                if (v2 < v || (v2 == v && i2 < li)) { v = v2; li = i2; }
            }
            if (lane == 0) {
                g_cv[base + pass] = v;
                g_ci[base + pass] = n0 + li;
                sh_c[w][li] = INFINITY;
            }
            __syncwarp(FULL);
        }
    }
}

// ---------------------------------------------------------------------------
// Kernel 2: partial cls-neg reduction over sb. grid (8, 2, NCLSPART).
// ---------------------------------------------------------------------------
__global__ __launch_bounds__(256) void cls_kernel()
{
    const int n = blockIdx.x * 256 + threadIdx.x;
    const int branch = blockIdx.y;
    const int part   = blockIdx.z;
    if (n >= NPRIOR) return;
    const float* base = g_cneg + ((size_t)branch * SB + part * SBPART) * NPRIOR + n;
    float acc = 0.0f;
    #pragma unroll
    for (int i = 0; i < SBPART; i++) acc += base[(size_t)i * NPRIOR];
    g_cls_part[((size_t)part * 2 + branch) * NPRIOR + n] = acc;
}

// ---------------------------------------------------------------------------
// Kernel 3: greedy merge + reg/iou + corrections + radix-select median +
//           final weighted sum. Single block, 1024 threads.
// ---------------------------------------------------------------------------
__global__ __launch_bounds__(1024) void final_kernel(
    const float* __restrict__ predA,
    const float* __restrict__ predB,
    const float* __restrict__ gt,
    const float* __restrict__ diff,
    float* __restrict__ out)
{
    __shared__ float instA[NPRIOR];
    __shared__ float instB[NPRIOR];
    __shared__ unsigned ukey[NPRIOR];
    __shared__ float reg_sh[NMATCH];
    __shared__ float iou_sh[NMATCH];
    __shared__ int   rows_sh[NMATCH];
    __shared__ int   hist[256];
    __shared__ float red[1024];
    __shared__ int   s_bin, s_k;

    const int tid = threadIdx.x;
    const unsigned FULL = 0xffffffffu;

    // ---- (a) greedy assignment: thread-per-(branch,sb) task over candidates ----
    if (tid < 2 * SB) {
        const int branch = tid / SB;
        const int sb     = tid % SB;
        const size_t bs  = (size_t)branch * SB + sb;
        int used[3];
        #pragma unroll
        for (int col = 0; col < LANES; col++) {
            const size_t base = (bs * LANES + col) * NCAND;
            float best = INFINITY; int bi = INT_MAX;
            for (int j = 0; j < NCAND; j++) {
                int i = g_ci[base + j];
                bool excl = false;
                #pragma unroll
                for (int u = 0; u < 3; u++) excl |= (u < col && i == used[u]);
                if (excl) continue;
                float v = g_cv[base + j];
                if (v < best || (v == best && i < bi)) { best = v; bi = i; }
            }
            rows_sh[bs * LANES + col] = bi;
            if (col < 3) used[col] = bi;
        }
    }

    // ---- init inst from cls partials ----
    for (int n = tid; n < NPRIOR; n += 1024) {
        float a0 = g_cls_part[0 * NPRIOR + n] + g_cls_part[2 * NPRIOR + n]
                 + g_cls_part[4 * NPRIOR + n] + g_cls_part[6 * NPRIOR + n];
        float b0 = g_cls_part[1 * NPRIOR + n] + g_cls_part[3 * NPRIOR + n]
                 + g_cls_part[5 * NPRIOR + n] + g_cls_part[7 * NPRIOR + n];
        instA[n] = a0 * (2.0f / 96.0f);
        instB[n] = b0 * (2.0f / 96.0f);
    }
    __syncthreads();

    // ---- (b) reg + iou: warp-per-match ----
    {
        const int warp = tid >> 5, lane = tid & 31;
        for (int mm = warp; mm < NMATCH; mm += 32) {
            const int branch = mm / (SB * LANES);
            const int rem    = mm % (SB * LANES);
            const int sb     = rem / LANES;
            const int l      = rem % LANES;
            const int b      = sb % BATCH;
            const int r      = rows_sh[mm];
            const float* p  = (branch ? predB : predA)
                              + ((size_t)sb * NPRIOR + r) * DFEAT;
            const float* tg = gt + ((size_t)b * LANES + l) * DFEAT;

            float ovrS = 0.0f, uniS = 0.0f;
            for (int k = lane; k < NOFF; k += 32) {
                float rp = p[6 + k] * IMG_W1_F;
                float rt = tg[6 + k];
                bool invalid = (rt < 0.0f) || (rt >= IMG_W_F);
                float mn = fminf(rp, rt), mx = fmaxf(rp, rt);
                if (!invalid) {
                    ovrS += (mn - mx + 30.0f);
                    uniS += (mx - mn + 30.0f);
                }
            }
            #pragma unroll
            for (int off = 16; off; off >>= 1) {
                ovrS += __shfl_xor_sync(FULL, ovrS, off);
                uniS += __shfl_xor_sync(FULL, uniS, off);
            }
            if (lane == 0) {
                float iou = ovrS / (uniS + 1e-9f);
                iou_sh[mm] = (1.0f - iou) * 0.25f;
                const float sc[4] = {71.0f, IMG_W1_F, 180.0f, 71.0f};
                float ssum = 0.0f;
                #pragma unroll
                for (int j = 0; j < 4; j++) {
                    float d  = (p[2 + j] - tg[2 + j]) * sc[j];
                    float ad = fabsf(d);
                    ssum += (ad < 1.0f) ? 0.5f * d * d : ad - 0.5f;
                }
                reg_sh[mm] = ssum * 0.0625f;   // mean over 4, /L
            }
        }
    }
    __syncthreads();

    // ---- (c) corrections into inst ----
    if (tid < NMATCH) {
        const int branch = tid / (SB * LANES);
        const int rem    = tid % (SB * LANES);
        const int sb     = rem / LANES;
        const int r      = rows_sh[tid];
        const size_t idx = ((size_t)branch * SB + sb) * NPRIOR + r;
        float corr = (g_cpos[idx] - g_cneg[idx]) * (2.0f / 96.0f);
        atomicAdd(branch == 0 ? &instA[r] : &instB[r], corr);
    }
    if (tid >= 1016) {   // 8 threads: reg/iou sums + scatter at rows[-1,-1]
        const int t = tid - 1016;
        const int branch = t >> 2, l = t & 3;
        float rs = 0.0f, is = 0.0f;
        #pragma unroll 8
        for (int i = 0; i < SB; i++) {
            rs += reg_sh[(branch * SB + i) * LANES + l];
            is += iou_sh[(branch * SB + i) * LANES + l];
        }
        float add = rs * (0.5f / 96.0f) + is * (2.0f / 96.0f);
        int r = rows_sh[(branch * SB + (SB - 1)) * LANES + l];
        atomicAdd(branch == 0 ? &instA[r] : &instB[r], add);
    }
    __syncthreads();

    // ---- (d) median via radix select (warp-parallel bin scan) ----
    for (int n = tid; n < NPRIOR; n += 1024) {
        float f = instA[n] - instB[n];
        unsigned x = __float_as_uint(f);
        ukey[n] = (x & 0x80000000u) ? ~x : (x | 0x80000000u);
    }
    __syncthreads();

    float medv[2];
    #pragma unroll
    for (int which = 0; which < 2; which++) {
        int kk = 999 + which;
        unsigned prefix = 0, mask = 0;
        for (int shift = 24; shift >= 0; shift -= 8) {
            if (tid < 256) hist[tid] = 0;
            __syncthreads();
            for (int n = tid; n < NPRIOR; n += 1024) {
                unsigned u = ukey[n];
                if ((u & mask) == prefix)
                    atomicAdd(&hist[(u >> shift) & 255], 1);
            }
            __syncthreads();
            if (tid < 32) {
                int cnt[8]; int local = 0;
                #pragma unroll
                for (int k2 = 0; k2 < 8; k2++) { cnt[k2] = hist[tid * 8 + k2]; local += cnt[k2]; }
                int pre = local;
                #pragma unroll
                for (int off = 1; off < 32; off <<= 1) {
                    int t2 = __shfl_up_sync(FULL, pre, off);
                    if (tid >= off) pre += t2;
                }
                int run = pre - local;       // exclusive prefix of this lane's 8 bins
                int foundk = -1, myrun = 0;
                #pragma unroll
                for (int k2 = 0; k2 < 8; k2++) {
                    if (foundk < 0 && kk >= run && kk < run + cnt[k2]) { foundk = k2; myrun = run; }
                    run += cnt[k2];
                }
                unsigned bm = __ballot_sync(FULL, foundk >= 0);
                int src = __ffs(bm) - 1;
                if (tid == src) { s_bin = tid * 8 + foundk; s_k = kk - myrun; }
            }
            __syncthreads();
            prefix |= ((unsigned)s_bin) << shift;
            mask   |= 0xFFu << shift;
            kk = s_k;
        }
        medv[which] = (prefix & 0x80000000u)
                      ? __uint_as_float(prefix ^ 0x80000000u)
                      : __uint_as_float(~prefix);
    }
    float delta = 0.5f * (medv[0] + medv[1]);

    // ---- (e) final weighted sum ----
    float acc = 0.0f;
    for (int n = tid; n < NPRIOR; n += 1024) {
        float dm = (diff[n] + diff[NPRIOR + n] + diff[2 * NPRIOR + n]) * (1.0f / 3.0f);
        acc += (1.0f - dm) * (instA[n] - 0.5f * delta)
             + dm          * (instB[n] + 0.5f * delta);
    }
    red[tid] = acc;
    __syncthreads();
    for (int off = 512; off; off >>= 1) {
        if (tid < off) red[tid] += red[tid + off];
        __syncthreads();
    }
    if (tid == 0) out[0] = red[0];
}

// ---------------------------------------------------------------------------
extern "C" void kernel_launch(void* const* d_in, const int* in_sizes, int n_in,
                              void* d_out, int out_size)
{
    const float* fir  = (const float*)d_in[0];
    const float* sec  = (const float*)d_in[1];
    const float* gt   = (const float*)d_in[2];
    const float* diff = (const float*)d_in[3];
    float* out = (float*)d_out;

    cost_kernel <<<dim3(SB, NTILE, 2), TILE>>>(fir, sec, gt);
    cls_kernel  <<<dim3((NPRIOR + 255) / 256, 2, NCLSPART), 256>>>();
    final_kernel<<<1, 1024>>>(fir, sec, gt, diff, out);
}

// round 6
// speedup vs baseline: 2.7884x; 2.4446x over previous
#include <cuda_runtime.h>
#include <math.h>
#include <limits.h>

#define S_STAGES 3
#define BATCH    32
#define NPRIOR   2000
#define LANES    4
#define DFEAT    78          // 2 + 4 + 72
#define NOFF     72
#define SB       96
#define IMG_W_F  800.0f
#define IMG_W1_F 799.0f
#define TILE     128
#define NTILE    16          // 15 full tiles + one of 80
#define RPAD     84          // padded row stride (floats): conflict-free LDS.128
#define NCAND    (NTILE * 4) // 64 candidates per column
#define NMATCH   (2 * SB * LANES)   // 768
#define NCLSPART 4
#define SBPART   (SB / NCLSPART)

// Scratch (device globals — no allocation allowed)
__device__ float g_cneg[2 * SB * NPRIOR];
__device__ float g_cpos[2 * SB * NPRIOR];
__device__ float g_cv[2 * SB * LANES * NCAND];
__device__ int   g_ci[2 * SB * LANES * NCAND];
__device__ float g_cls_part[NCLSPART * 2 * NPRIOR];

__device__ __forceinline__ void cp_async8(unsigned s, const void* g) {
    asm volatile("cp.async.ca.shared.global [%0], [%1], 8;\n" :: "r"(s), "l"(g));
}
__device__ __forceinline__ void cp_commit() {
    asm volatile("cp.async.commit_group;\n" ::: "memory");
}
__device__ __forceinline__ void cp_wait0() {
    asm volatile("cp.async.wait_group 0;\n" ::: "memory");
}

// ---------------------------------------------------------------------------
// Kernel 1: thread-per-prior cost + focal terms + per-tile top-4 candidates.
// grid (96, NTILE, 2), 128 threads. cp.async-staged tile (fire-and-forget).
// ---------------------------------------------------------------------------
__global__ __launch_bounds__(TILE) void cost_kernel(
    const float* __restrict__ predA,
    const float* __restrict__ predB,
    const float* __restrict__ gt)
{
    const int sb     = blockIdx.x;
    const int tile   = blockIdx.y;
    const int branch = blockIdx.z;
    const int n0     = tile * TILE;
    const int T      = (n0 + TILE <= NPRIOR) ? TILE : (NPRIOR - n0);
    const float* __restrict__ pred = branch ? predB : predA;
    const int b = sb % BATCH;
    const float* gbase = pred + ((size_t)sb * NPRIOR + n0) * DFEAT;
    const size_t bs = (size_t)branch * SB + sb;

    __shared__ __align__(16) float sh_pred[TILE * RPAD];   // 43008 B
    __shared__ __align__(16) float sh_goff[LANES][80];     // by dim, zeros outside [6,78)
    __shared__ float sh_geo[LANES][4];
    __shared__ float sh_c[LANES][TILE];

    const int tid  = threadIdx.x;
    const int warp = tid >> 5, lane = tid & 31;
    const unsigned FULL = 0xffffffffu;
    const unsigned sp = (unsigned)__cvta_generic_to_shared(sh_pred);

    // stage tile via cp.async: flat float2 copies (rows 8B-aligned, stride 312B)
    {
        const int total = T * 39;                      // float2 count
        for (int f = tid; f < total; f += TILE) {
            int row = f / 39, c2 = f - row * 39;
            cp_async8(sp + (unsigned)(row * 336 + c2 * 8),
                      (const char*)gbase + (size_t)row * 312 + c2 * 8);
        }
        cp_commit();
    }

    // gt offsets (by dim index, padded with zeros) + geo dims — overlap with cp.async
    for (int i = tid; i < LANES * 80; i += TILE) {
        int l = i / 80, d = i % 80;
        float v = 0.0f;
        if (d >= 6 && d < DFEAT)
            v = gt[((size_t)b * LANES + l) * DFEAT + d] * (1.0f / IMG_W1_F);
        sh_goff[l][d] = v;
    }
    if (tid < 16)
        sh_geo[tid >> 2][tid & 3] =
            gt[((size_t)b * LANES + (tid >> 2)) * DFEAT + 2 + (tid & 3)];
    // zero pad floats 78,79 of each staged row
    if (tid < T) {
        sh_pred[tid * RPAD + 78] = 0.0f;
        sh_pred[tid * RPAD + 79] = 0.0f;
    }

    cp_wait0();
    __syncthreads();

    if (tid < T) {
        const float* rp = sh_pred + tid * RPAD;
        float4 p0 = *reinterpret_cast<const float4*>(rp);       // dims 0-3
        float4 p1 = *reinterpret_cast<const float4*>(rp + 4);   // dims 4-7

        float cg[LANES], o[LANES];
        #pragma unroll
        for (int l = 0; l < LANES; l++) {
            cg[l] = fabsf(p0.z - sh_geo[l][0]) + fabsf(p0.w - sh_geo[l][1])
                  + fabsf(p1.x - sh_geo[l][2]) + fabsf(p1.y - sh_geo[l][3]);
            o[l]  = fabsf(p1.z - sh_goff[l][6]) + fabsf(p1.w - sh_goff[l][7]);
        }
        #pragma unroll
        for (int c = 2; c < 20; c++) {                           // dims 8..79
            float4 pv = *reinterpret_cast<const float4*>(rp + 4 * c);
            #pragma unroll
            for (int l = 0; l < LANES; l++) {
                float4 gv = *reinterpret_cast<const float4*>(&sh_goff[l][4 * c]);
                o[l] += fabsf(pv.x - gv.x) + fabsf(pv.y - gv.y)
                      + fabsf(pv.z - gv.z) + fabsf(pv.w - gv.w);
            }
        }

        float x0 = p0.x, x1 = p0.y;
        float m  = fmaxf(x0, x1);
        float e0 = expf(x0 - m), e1 = expf(x1 - m);
        float denom = e0 + e1;
        float score = e1 / denom;
        #pragma unroll
        for (int l = 0; l < LANES; l++)
            sh_c[l][tid] = cg[l] + o[l] * (1.0f / 72.0f) - score;

        float lse = m + logf(denom);
        float pt0 = e0 / denom;
        float om0 = 1.0f - pt0, om1 = 1.0f - score;
        g_cneg[bs * NPRIOR + n0 + tid] = -0.1f * om0 * om0 * (x0 - lse);
        g_cpos[bs * NPRIOR + n0 + tid] = -0.9f * om1 * om1 * (x1 - lse);
    } else {
        #pragma unroll
        for (int l = 0; l < LANES; l++) sh_c[l][tid] = INFINITY;
    }
    __syncthreads();

    // warp w: top-4 (value,index) of column w within tile, first-index tie-break
    {
        const int w = warp;
        const size_t base = ((bs * LANES + w) * NTILE + tile) * 4;
        #pragma unroll
        for (int pass = 0; pass < 4; pass++) {
            float v = INFINITY; int li = INT_MAX;
            #pragma unroll
            for (int j0 = 0; j0 < TILE; j0 += 32) {
                int j = j0 + lane;
                float cc = sh_c[w][j];
                if (cc < v || (cc == v && j < li)) { v = cc; li = j; }
            }
            #pragma unroll
            for (int off = 16; off; off >>= 1) {
                float v2 = __shfl_xor_sync(FULL, v, off);
                int   i2 = __shfl_xor_sync(FULL, li, off);
                if (v2 < v || (v2 == v && i2 < li)) { v = v2; li = i2; }
            }
            if (lane == 0) {
                g_cv[base + pass] = v;
                g_ci[base + pass] = n0 + li;
                sh_c[w][li] = INFINITY;
            }
            __syncwarp(FULL);
        }
    }
}

// ---------------------------------------------------------------------------
// Kernel 2: partial cls-neg reduction over sb. grid (8, 2, NCLSPART).
// ---------------------------------------------------------------------------
__global__ __launch_bounds__(256) void cls_kernel()
{
    const int n = blockIdx.x * 256 + threadIdx.x;
    const int branch = blockIdx.y;
    const int part   = blockIdx.z;
    if (n >= NPRIOR) return;
    const float* base = g_cneg + ((size_t)branch * SB + part * SBPART) * NPRIOR + n;
    float acc = 0.0f;
    #pragma unroll
    for (int i = 0; i < SBPART; i++) acc += base[(size_t)i * NPRIOR];
    g_cls_part[((size_t)part * 2 + branch) * NPRIOR + n] = acc;
}

// ---------------------------------------------------------------------------
// Kernel 3: warp-parallel greedy merge + reg/iou + corrections + radix-select
//           median + final weighted sum. Single block, 1024 threads.
// ---------------------------------------------------------------------------
__global__ __launch_bounds__(1024) void final_kernel(
    const float* __restrict__ predA,
    const float* __restrict__ predB,
    const float* __restrict__ gt,
    const float* __restrict__ diff,
    float* __restrict__ out)
{
    __shared__ float instA[NPRIOR];
    __shared__ float instB[NPRIOR];
    __shared__ unsigned ukey[NPRIOR];
    __shared__ float reg_sh[NMATCH];
    __shared__ float iou_sh[NMATCH];
    __shared__ int   rows_sh[NMATCH];
    __shared__ int   hist[256];
    __shared__ float red[1024];
    __shared__ int   s_bin, s_k;

    const int tid = threadIdx.x;
    const int warp = tid >> 5, lane = tid & 31;
    const unsigned FULL = 0xffffffffu;

    // ---- (a) greedy assignment: warp-per-(branch,sb) task, 6 rounds ----
    #pragma unroll
    for (int round = 0; round < 6; round++) {
        const int task = warp + 32 * round;            // 0..191
        const size_t base = (size_t)task * LANES * NCAND;
        // preload all candidates: 4 cols x 2 per lane
        float cv[LANES][2]; int ci[LANES][2];
        #pragma unroll
        for (int col = 0; col < LANES; col++) {
            cv[col][0] = g_cv[base + col * NCAND + lane];
            cv[col][1] = g_cv[base + col * NCAND + 32 + lane];
            ci[col][0] = g_ci[base + col * NCAND + lane];
            ci[col][1] = g_ci[base + col * NCAND + 32 + lane];
        }
        int u0 = -1, u1 = -1, u2 = -1;
        #pragma unroll
        for (int col = 0; col < LANES; col++) {
            float v = INFINITY; int li = INT_MAX;
            #pragma unroll
            for (int k = 0; k < 2; k++) {
                int   i2 = ci[col][k];
                float v2 = cv[col][k];
                bool excl = (i2 == u0) | (i2 == u1) | (i2 == u2);
                if (!excl && (v2 < v || (v2 == v && i2 < li))) { v = v2; li = i2; }
            }
            #pragma unroll
            for (int off = 16; off; off >>= 1) {
                float v2 = __shfl_xor_sync(FULL, v, off);
                int   i2 = __shfl_xor_sync(FULL, li, off);
                if (v2 < v || (v2 == v && i2 < li)) { v = v2; li = i2; }
            }
            if (lane == 0) rows_sh[task * LANES + col] = li;
            if (col == 0) u0 = li; else if (col == 1) u1 = li; else if (col == 2) u2 = li;
        }
    }

    // ---- init inst from cls partials ----
    for (int n = tid; n < NPRIOR; n += 1024) {
        float a0 = g_cls_part[0 * NPRIOR + n] + g_cls_part[2 * NPRIOR + n]
                 + g_cls_part[4 * NPRIOR + n] + g_cls_part[6 * NPRIOR + n];
        float b0 = g_cls_part[1 * NPRIOR + n] + g_cls_part[3 * NPRIOR + n]
                 + g_cls_part[5 * NPRIOR + n] + g_cls_part[7 * NPRIOR + n];
        instA[n] = a0 * (2.0f / 96.0f);
        instB[n] = b0 * (2.0f / 96.0f);
    }
    __syncthreads();

    // ---- (b) reg + iou: warp-per-match, unrolled for MLP ----
    #pragma unroll 2
    for (int mm = warp; mm < NMATCH; mm += 32) {
        const int branch = mm / (SB * LANES);
        const int rem    = mm % (SB * LANES);
        const int sb     = rem / LANES;
        const int l      = rem % LANES;
        const int b      = sb % BATCH;
        const int r      = rows_sh[mm];
        const float* p  = (branch ? predB : predA)
                          + ((size_t)sb * NPRIOR + r) * DFEAT;
        const float* tg = gt + ((size_t)b * LANES + l) * DFEAT;

        float ovrS = 0.0f, uniS = 0.0f;
        #pragma unroll
        for (int kb = 0; kb < 3; kb++) {
            int k = kb * 32 + lane;
            if (k < NOFF) {
                float rp = p[6 + k] * IMG_W1_F;
                float rt = tg[6 + k];
                bool invalid = (rt < 0.0f) || (rt >= IMG_W_F);
                float mn = fminf(rp, rt), mx = fmaxf(rp, rt);
                if (!invalid) {
                    ovrS += (mn - mx + 30.0f);
                    uniS += (mx - mn + 30.0f);
                }
            }
        }
        #pragma unroll
        for (int off = 16; off; off >>= 1) {
            ovrS += __shfl_xor_sync(FULL, ovrS, off);
            uniS += __shfl_xor_sync(FULL, uniS, off);
        }
        if (lane == 0) {
            float iou = ovrS / (uniS + 1e-9f);
            iou_sh[mm] = (1.0f - iou) * 0.25f;
            const float sc[4] = {71.0f, IMG_W1_F, 180.0f, 71.0f};
            float ssum = 0.0f;
            #pragma unroll
            for (int j = 0; j < 4; j++) {
                float d  = (p[2 + j] - tg[2 + j]) * sc[j];
                float ad = fabsf(d);
                ssum += (ad < 1.0f) ? 0.5f * d * d : ad - 0.5f;
            }
            reg_sh[mm] = ssum * 0.0625f;   // mean over 4, /L
        }
    }
    __syncthreads();

    // ---- (c) corrections into inst ----
    if (tid < NMATCH) {
        const int branch = tid / (SB * LANES);
        const int rem    = tid % (SB * LANES);
        const int sb     = rem / LANES;
        const int r      = rows_sh[tid];
        const size_t idx = ((size_t)branch * SB + sb) * NPRIOR + r;
        float corr = (g_cpos[idx] - g_cneg[idx]) * (2.0f / 96.0f);
        atomicAdd(branch == 0 ? &instA[r] : &instB[r], corr);
    }
    if (tid >= 1016) {   // 8 threads: reg/iou sums + scatter at rows[-1,-1]
        const int t = tid - 1016;
        const int branch = t >> 2, l = t & 3;
        float rs = 0.0f, is = 0.0f;
        #pragma unroll 8
        for (int i = 0; i < SB; i++) {
            rs += reg_sh[(branch * SB + i) * LANES + l];
            is += iou_sh[(branch * SB + i) * LANES + l];
        }
        float add = rs * (0.5f / 96.0f) + is * (2.0f / 96.0f);
        int r = rows_sh[(branch * SB + (SB - 1)) * LANES + l];
        atomicAdd(branch == 0 ? &instA[r] : &instB[r], add);
    }
    __syncthreads();

    // ---- (d) median via radix select (warp-parallel bin scan) ----
    for (int n = tid; n < NPRIOR; n += 1024) {
        float f = instA[n] - instB[n];
        unsigned x = __float_as_uint(f);
        ukey[n] = (x & 0x80000000u) ? ~x : (x | 0x80000000u);
    }
    __syncthreads();

    float medv[2];
    #pragma unroll
    for (int which = 0; which < 2; which++) {
        int kk = 999 + which;
        unsigned prefix = 0, mask = 0;
        for (int shift = 24; shift >= 0; shift -= 8) {
            if (tid < 256) hist[tid] = 0;
            __syncthreads();
            for (int n = tid; n < NPRIOR; n += 1024) {
                unsigned u = ukey[n];
                if ((u & mask) == prefix)
                    atomicAdd(&hist[(u >> shift) & 255], 1);
            }
            __syncthreads();
            if (tid < 32) {
                int cnt[8]; int local = 0;
                #pragma unroll
                for (int k2 = 0; k2 < 8; k2++) { cnt[k2] = hist[tid * 8 + k2]; local += cnt[k2]; }
                int pre = local;
                #pragma unroll
                for (int off = 1; off < 32; off <<= 1) {
                    int t2 = __shfl_up_sync(FULL, pre, off);
                    if (tid >= off) pre += t2;
                }
                int run = pre - local;       // exclusive prefix of this lane's 8 bins
                int foundk = -1, myrun = 0;
                #pragma unroll
                for (int k2 = 0; k2 < 8; k2++) {
                    if (foundk < 0 && kk >= run && kk < run + cnt[k2]) { foundk = k2; myrun = run; }
                    run += cnt[k2];
                }
                unsigned bm = __ballot_sync(FULL, foundk >= 0);
                int src = __ffs(bm) - 1;
                if (tid == src) { s_bin = tid * 8 + foundk; s_k = kk - myrun; }
            }
            __syncthreads();
            prefix |= ((unsigned)s_bin) << shift;
            mask   |= 0xFFu << shift;
            kk = s_k;
        }
        medv[which] = (prefix & 0x80000000u)
                      ? __uint_as_float(prefix ^ 0x80000000u)
                      : __uint_as_float(~prefix);
    }
    float delta = 0.5f * (medv[0] + medv[1]);

    // ---- (e) final weighted sum ----
    float acc = 0.0f;
    for (int n = tid; n < NPRIOR; n += 1024) {
        float dm = (diff[n] + diff[NPRIOR + n] + diff[2 * NPRIOR + n]) * (1.0f / 3.0f);
        acc += (1.0f - dm) * (instA[n] - 0.5f * delta)
             + dm          * (instB[n] + 0.5f * delta);
    }
    red[tid] = acc;
    __syncthreads();
    for (int off = 512; off; off >>= 1) {
        if (tid < off) red[tid] += red[tid + off];
        __syncthreads();
    }
    if (tid == 0) out[0] = red[0];
}

// ---------------------------------------------------------------------------
extern "C" void kernel_launch(void* const* d_in, const int* in_sizes, int n_in,
                              void* d_out, int out_size)
{
    const float* fir  = (const float*)d_in[0];
    const float* sec  = (const float*)d_in[1];
    const float* gt   = (const float*)d_in[2];
    const float* diff = (const float*)d_in[3];
    float* out = (float*)d_out;

    cost_kernel <<<dim3(SB, NTILE, 2), TILE>>>(fir, sec, gt);
    cls_kernel  <<<dim3((NPRIOR + 255) / 256, 2, NCLSPART), 256>>>();
    final_kernel<<<1, 1024>>>(fir, sec, gt, diff, out);
}

// round 7
// speedup vs baseline: 2.8410x; 1.0189x over previous
#include <cuda_runtime.h>
#include <math.h>
#include <limits.h>

#define S_STAGES 3
#define BATCH    32
#define NPRIOR   2000
#define LANES    4
#define DFEAT    78          // 2 + 4 + 72
#define NOFF     72
#define SB       96
#define IMG_W_F  800.0f
#define IMG_W1_F 799.0f
#define TILE     128
#define NTILE    16          // 15 full tiles + one of 80
#define RP2      44          // buffer row stride (floats), conflict-free LDS.128
#define NCAND    (NTILE * 4) // 64 candidates per column
#define NMATCH   (2 * SB * LANES)   // 768
#define FIXSCALE 1099511627776.0f   // 2^40

// Scratch (device globals — no allocation allowed)
// g_cls_acc is zero at load; final_kernel re-zeroes it after consuming (replay-safe).
__device__ unsigned long long g_cls_acc[2 * NPRIOR];
__device__ float g_cv[2 * SB * LANES * NCAND];
__device__ int   g_ci[2 * SB * LANES * NCAND];

__device__ __forceinline__ void cp_async8(unsigned s, const void* g) {
    asm volatile("cp.async.ca.shared.global [%0], [%1], 8;\n" :: "r"(s), "l"(g));
}
__device__ __forceinline__ void cp_commit() {
    asm volatile("cp.async.commit_group;\n" ::: "memory");
}
__device__ __forceinline__ void cp_wait0() {
    asm volatile("cp.async.wait_group 0;\n" ::: "memory");
}

// ---------------------------------------------------------------------------
// Kernel 1: two-phase staged cost + candidate top-4 + fixed-point cls RED.
// grid (96, NTILE, 2), 128 threads. ~26 KB SMEM -> 8 blocks/SM.
// ---------------------------------------------------------------------------
__global__ __launch_bounds__(TILE) void cost_kernel(
    const float* __restrict__ predA,
    const float* __restrict__ predB,
    const float* __restrict__ gt)
{
    const int sb     = blockIdx.x;
    const int tile   = blockIdx.y;
    const int branch = blockIdx.z;
    const int n0     = tile * TILE;
    const int T      = (n0 + TILE <= NPRIOR) ? TILE : (NPRIOR - n0);
    const float* __restrict__ pred = branch ? predB : predA;
    const int b = sb % BATCH;
    const char* gbase = (const char*)(pred + ((size_t)sb * NPRIOR + n0) * DFEAT);
    const size_t bs = (size_t)branch * SB + sb;

    __shared__ __align__(16) float sh_buf[TILE * RP2];     // 22528 B
    __shared__ __align__(16) float sh_goff[LANES][80];     // by dim, zeros outside [6,78)
    __shared__ float sh_geo[LANES][4];
    __shared__ float sh_c[LANES][TILE];

    const int tid  = threadIdx.x;
    const int warp = tid >> 5, lane = tid & 31;
    const unsigned FULL = 0xffffffffu;
    const unsigned sp = (unsigned)__cvta_generic_to_shared(sh_buf);

    // ---- stage phase A: dims 0..39 (20 x 8B chunks per row), coalesced flat map
    {
        int row = tid / 20, c2 = tid - row * 20, f = tid;
        const int total = T * 20;
        while (f < total) {
            cp_async8(sp + (unsigned)(row * (RP2 * 4) + c2 * 8),
                      gbase + (size_t)row * 312 + c2 * 8);
            f += 128; row += 6; c2 += 8;
            if (c2 >= 20) { c2 -= 20; row += 1; }
        }
        cp_commit();
    }

    // gt tables (overlap with cp.async)
    for (int i = tid; i < LANES * 80; i += TILE) {
        int l = i / 80, d = i % 80;
        float v = 0.0f;
        if (d >= 6 && d < DFEAT)
            v = gt[((size_t)b * LANES + l) * DFEAT + d] * (1.0f / IMG_W1_F);
        sh_goff[l][d] = v;
    }
    if (tid < 16)
        sh_geo[tid >> 2][tid & 3] =
            gt[((size_t)b * LANES + (tid >> 2)) * DFEAT + 2 + (tid & 3)];

    cp_wait0();
    __syncthreads();

    // ---- compute phase A: dims 0..39
    float cg[LANES], o[LANES];
    float score = 0.0f;
    if (tid < T) {
        const float* rp = sh_buf + tid * RP2;
        float4 p0 = *reinterpret_cast<const float4*>(rp);       // dims 0-3
        float4 p1 = *reinterpret_cast<const float4*>(rp + 4);   // dims 4-7
        #pragma unroll
        for (int l = 0; l < LANES; l++) {
            cg[l] = fabsf(p0.z - sh_geo[l][0]) + fabsf(p0.w - sh_geo[l][1])
                  + fabsf(p1.x - sh_geo[l][2]) + fabsf(p1.y - sh_geo[l][3]);
            o[l]  = fabsf(p1.z - sh_goff[l][6]) + fabsf(p1.w - sh_goff[l][7]);
        }
        #pragma unroll
        for (int c = 2; c < 10; c++) {                           // dims 8..39
            float4 pv = *reinterpret_cast<const float4*>(rp + 4 * c);
            #pragma unroll
            for (int l = 0; l < LANES; l++) {
                float4 gv = *reinterpret_cast<const float4*>(&sh_goff[l][4 * c]);
                o[l] += fabsf(pv.x - gv.x) + fabsf(pv.y - gv.y)
                      + fabsf(pv.z - gv.z) + fabsf(pv.w - gv.w);
            }
        }
        float x0 = p0.x, x1 = p0.y;
        float m  = fmaxf(x0, x1);
        float e0 = expf(x0 - m), e1 = expf(x1 - m);
        float denom = e0 + e1;
        score = e1 / denom;
        // unmatched focal term, fixed-point RED (deterministic)
        float lse = m + logf(denom);
        float om0 = 1.0f - e0 / denom;
        float cneg = -0.1f * om0 * om0 * (x0 - lse);
        atomicAdd(&g_cls_acc[branch * NPRIOR + n0 + tid],
                  (unsigned long long)(long long)__float2ll_rn(cneg * FIXSCALE));
    }
    __syncthreads();   // phase-A buffer reads complete

    // ---- stage phase B: dims 40..77 (19 x 8B chunks per row) + zero pad cols 38,39
    {
        int row = tid / 19, c2 = tid - row * 19, f = tid;
        const int total = T * 19;
        while (f < total) {
            cp_async8(sp + (unsigned)(row * (RP2 * 4) + c2 * 8),
                      gbase + (size_t)row * 312 + 160 + c2 * 8);
            f += 128; row += 6; c2 += 14;
            if (c2 >= 19) { c2 -= 19; row += 1; }
        }
        cp_commit();
    }
    if (tid < T) {
        sh_buf[tid * RP2 + 38] = 0.0f;
        sh_buf[tid * RP2 + 39] = 0.0f;
    }
    cp_wait0();
    __syncthreads();

    // ---- compute phase B: dims 40..77 (cols 0..37; 38,39 zero vs goff zero)
    if (tid < T) {
        const float* rp = sh_buf + tid * RP2;
        #pragma unroll
        for (int c = 0; c < 10; c++) {
            float4 pv = *reinterpret_cast<const float4*>(rp + 4 * c);
            #pragma unroll
            for (int l = 0; l < LANES; l++) {
                float4 gv = *reinterpret_cast<const float4*>(&sh_goff[l][40 + 4 * c]);
                o[l] += fabsf(pv.x - gv.x) + fabsf(pv.y - gv.y)
                      + fabsf(pv.z - gv.z) + fabsf(pv.w - gv.w);
            }
        }
        #pragma unroll
        for (int l = 0; l < LANES; l++)
            sh_c[l][tid] = cg[l] + o[l] * (1.0f / 72.0f) - score;
    } else {
        #pragma unroll
        for (int l = 0; l < LANES; l++) sh_c[l][tid] = INFINITY;
    }
    __syncthreads();

    // ---- warp w: top-4 of column w within tile, first-index tie-break
    {
        const int w = warp;
        const size_t base = ((bs * LANES + w) * NTILE + tile) * 4;
        #pragma unroll
        for (int pass = 0; pass < 4; pass++) {
            float v = INFINITY; int li = INT_MAX;
            #pragma unroll
            for (int j0 = 0; j0 < TILE; j0 += 32) {
                int j = j0 + lane;
                float cc = sh_c[w][j];
                if (cc < v || (cc == v && j < li)) { v = cc; li = j; }
            }
            #pragma unroll
            for (int off = 16; off; off >>= 1) {
                float v2 = __shfl_xor_sync(FULL, v, off);
                int   i2 = __shfl_xor_sync(FULL, li, off);
                if (v2 < v || (v2 == v && i2 < li)) { v = v2; li = i2; }
            }
            if (lane == 0) {
                g_cv[base + pass] = v;
                g_ci[base + pass] = n0 + li;
                sh_c[w][li] = INFINITY;
            }
            __syncwarp(FULL);
        }
    }
}

// ---------------------------------------------------------------------------
// Kernel 2: greedy merge + reg/iou + focal corrections + dual-rank radix
//           median + final weighted sum. Single block, 1024 threads.
// ---------------------------------------------------------------------------
__global__ __launch_bounds__(1024) void final_kernel(
    const float* __restrict__ predA,
    const float* __restrict__ predB,
    const float* __restrict__ gt,
    const float* __restrict__ diff,
    float* __restrict__ out)
{
    __shared__ float instA[NPRIOR];
    __shared__ float instB[NPRIOR];
    __shared__ unsigned ukey[NPRIOR];
    __shared__ float reg_sh[NMATCH];
    __shared__ float iou_sh[NMATCH];
    __shared__ float corr_sh[NMATCH];
    __shared__ int   rows_sh[NMATCH];
    __shared__ int   hist[2][256];
    __shared__ float red[1024];
    __shared__ int   s_bin[2], s_k[2];

    const int tid = threadIdx.x;
    const int warp = tid >> 5, lane = tid & 31;
    const unsigned FULL = 0xffffffffu;

    // ---- (a) greedy assignment: warp-per-(branch,sb) task, 6 rounds ----
    #pragma unroll
    for (int round = 0; round < 6; round++) {
        const int task = warp + 32 * round;            // 0..191
        const size_t base = (size_t)task * LANES * NCAND;
        float cv[LANES][2]; int ci[LANES][2];
        #pragma unroll
        for (int col = 0; col < LANES; col++) {
            cv[col][0] = g_cv[base + col * NCAND + lane];
            cv[col][1] = g_cv[base + col * NCAND + 32 + lane];
            ci[col][0] = g_ci[base + col * NCAND + lane];
            ci[col][1] = g_ci[base + col * NCAND + 32 + lane];
        }
        int u0 = -1, u1 = -1, u2 = -1;
        #pragma unroll
        for (int col = 0; col < LANES; col++) {
            float v = INFINITY; int li = INT_MAX;
            #pragma unroll
            for (int k = 0; k < 2; k++) {
                int   i2 = ci[col][k];
                float v2 = cv[col][k];
                bool excl = (i2 == u0) | (i2 == u1) | (i2 == u2);
                if (!excl && (v2 < v || (v2 == v && i2 < li))) { v = v2; li = i2; }
            }
            #pragma unroll
            for (int off = 16; off; off >>= 1) {
                float v2 = __shfl_xor_sync(FULL, v, off);
                int   i2 = __shfl_xor_sync(FULL, li, off);
                if (v2 < v || (v2 == v && i2 < li)) { v = v2; li = i2; }
            }
            if (lane == 0) rows_sh[task * LANES + col] = li;
            if (col == 0) u0 = li; else if (col == 1) u1 = li; else if (col == 2) u2 = li;
        }
    }

    // ---- init inst from fixed-point cls accumulators, then restore zeros ----
    const float CLS_K = (float)(2.0 / 96.0 / 1099511627776.0);
    for (int n = tid; n < NPRIOR; n += 1024) {
        long long a0 = (long long)g_cls_acc[n];
        long long b0 = (long long)g_cls_acc[NPRIOR + n];
        instA[n] = (float)a0 * CLS_K;
        instB[n] = (float)b0 * CLS_K;
        g_cls_acc[n] = 0ull;                 // replay-safe invariant
        g_cls_acc[NPRIOR + n] = 0ull;
    }
    __syncthreads();

    // ---- (b) reg + iou + focal correction: warp-per-match ----
    #pragma unroll 2
    for (int mm = warp; mm < NMATCH; mm += 32) {
        const int branch = mm / (SB * LANES);
        const int rem    = mm % (SB * LANES);
        const int sb     = rem / LANES;
        const int l      = rem % LANES;
        const int b      = sb % BATCH;
        const int r      = rows_sh[mm];
        const float* p  = (branch ? predB : predA)
                          + ((size_t)sb * NPRIOR + r) * DFEAT;
        const float* tg = gt + ((size_t)b * LANES + l) * DFEAT;

        float ovrS = 0.0f, uniS = 0.0f;
        #pragma unroll
        for (int kb = 0; kb < 3; kb++) {
            int k = kb * 32 + lane;
            if (k < NOFF) {
                float rp = p[6 + k] * IMG_W1_F;
                float rt = tg[6 + k];
                bool invalid = (rt < 0.0f) || (rt >= IMG_W_F);
                float mn = fminf(rp, rt), mx = fmaxf(rp, rt);
                if (!invalid) {
                    ovrS += (mn - mx + 30.0f);
                    uniS += (mx - mn + 30.0f);
                }
            }
        }
        #pragma unroll
        for (int off = 16; off; off >>= 1) {
            ovrS += __shfl_xor_sync(FULL, ovrS, off);
            uniS += __shfl_xor_sync(FULL, uniS, off);
        }
        if (lane == 0) {
            float iou = ovrS / (uniS + 1e-9f);
            iou_sh[mm] = (1.0f - iou) * 0.25f;
            const float sc[4] = {71.0f, IMG_W1_F, 180.0f, 71.0f};
            float ssum = 0.0f;
            #pragma unroll
            for (int j = 0; j < 4; j++) {
                float d  = (p[2 + j] - tg[2 + j]) * sc[j];
                float ad = fabsf(d);
                ssum += (ad < 1.0f) ? 0.5f * d * d : ad - 0.5f;
            }
            reg_sh[mm] = ssum * 0.0625f;   // mean over 4, /L

            // focal correction (cpos - cneg), matching cost_kernel arithmetic
            float x0 = p[0], x1 = p[1];
            float m2  = fmaxf(x0, x1);
            float e0 = expf(x0 - m2), e1 = expf(x1 - m2);
            float denom = e0 + e1;
            float lse = m2 + logf(denom);
            float pt0 = e0 / denom, pt1 = e1 / denom;
            float om0 = 1.0f - pt0, om1 = 1.0f - pt1;
            float cneg = -0.1f * om0 * om0 * (x0 - lse);
            float cpos = -0.9f * om1 * om1 * (x1 - lse);
            corr_sh[mm] = (cpos - cneg) * (2.0f / 96.0f);
        }
    }
    __syncthreads();

    // ---- (c) corrections into inst ----
    if (tid < NMATCH) {
        const int branch = tid / (SB * LANES);
        const int r      = rows_sh[tid];
        atomicAdd(branch == 0 ? &instA[r] : &instB[r], corr_sh[tid]);
    }
    if (tid >= 1016) {   // 8 threads: reg/iou sums + scatter at rows[-1,-1]
        const int t = tid - 1016;
        const int branch = t >> 2, l = t & 3;
        float rs = 0.0f, is = 0.0f;
        #pragma unroll 8
        for (int i = 0; i < SB; i++) {
            rs += reg_sh[(branch * SB + i) * LANES + l];
            is += iou_sh[(branch * SB + i) * LANES + l];
        }
        float add = rs * (0.5f / 96.0f) + is * (2.0f / 96.0f);
        int r = rows_sh[(branch * SB + (SB - 1)) * LANES + l];
        atomicAdd(branch == 0 ? &instA[r] : &instB[r], add);
    }
    __syncthreads();

    // ---- (d) median via dual-rank radix select (4 passes, 2 tracks) ----
    for (int n = tid; n < NPRIOR; n += 1024) {
        float f = instA[n] - instB[n];
        unsigned x = __float_as_uint(f);
        ukey[n] = (x & 0x80000000u) ? ~x : (x | 0x80000000u);
    }
    __syncthreads();

    unsigned prefix[2] = {0u, 0u};
    unsigned mask = 0u;
    int kk[2] = {999, 1000};
    for (int shift = 24; shift >= 0; shift -= 8) {
        if (tid < 512) hist[tid >> 8][tid & 255] = 0;
        __syncthreads();
        for (int n = tid; n < NPRIOR; n += 1024) {
            unsigned u = ukey[n];
            unsigned bin = (u >> shift) & 255u;
            unsigned hi = u & mask;
            if (hi == prefix[0]) atomicAdd(&hist[0][bin], 1);
            if (hi == prefix[1]) atomicAdd(&hist[1][bin], 1);
        }
        __syncthreads();
        if (tid < 64) {              // warps 0,1 handle tracks 0,1
            const int trk = warp;
            int kt = kk[trk];
            int cnt[8]; int local = 0;
            #pragma unroll
            for (int k2 = 0; k2 < 8; k2++) { cnt[k2] = hist[trk][lane * 8 + k2]; local += cnt[k2]; }
            int pre = local;
            #pragma unroll
            for (int off = 1; off < 32; off <<= 1) {
                int t2 = __shfl_up_sync(FULL, pre, off);
                if (lane >= off) pre += t2;
            }
            int run = pre - local;
            int foundk = -1, myrun = 0;
            #pragma unroll
            for (int k2 = 0; k2 < 8; k2++) {
                if (foundk < 0 && kt >= run && kt < run + cnt[k2]) { foundk = k2; myrun = run; }
                run += cnt[k2];
            }
            unsigned bm = __ballot_sync(FULL, foundk >= 0);
            int src = __ffs(bm) - 1;
            if (lane == src) { s_bin[trk] = lane * 8 + foundk; s_k[trk] = kt - myrun; }
        }
        __syncthreads();
        prefix[0] |= ((unsigned)s_bin[0]) << shift;
        prefix[1] |= ((unsigned)s_bin[1]) << shift;
        mask |= 0xFFu << shift;
        kk[0] = s_k[0]; kk[1] = s_k[1];
        __syncthreads();
    }
    float m0 = (prefix[0] & 0x80000000u) ? __uint_as_float(prefix[0] ^ 0x80000000u)
                                         : __uint_as_float(~prefix[0]);
    float m1 = (prefix[1] & 0x80000000u) ? __uint_as_float(prefix[1] ^ 0x80000000u)
                                         : __uint_as_float(~prefix[1]);
    float delta = 0.5f * (m0 + m1);

    // ---- (e) final weighted sum ----
    float acc = 0.0f;
    for (int n = tid; n < NPRIOR; n += 1024) {
        float dm = (diff[n] + diff[NPRIOR + n] + diff[2 * NPRIOR + n]) * (1.0f / 3.0f);
        acc += (1.0f - dm) * (instA[n] - 0.5f * delta)
             + dm          * (instB[n] + 0.5f * delta);
    }
    red[tid] = acc;
    __syncthreads();
    for (int off = 512; off; off >>= 1) {
        if (tid < off) red[tid] += red[tid + off];
        __syncthreads();
    }
    if (tid == 0) out[0] = red[0];
}

// ---------------------------------------------------------------------------
extern "C" void kernel_launch(void* const* d_in, const int* in_sizes, int n_in,
                              void* d_out, int out_size)
{
    const float* fir  = (const float*)d_in[0];
    const float* sec  = (const float*)d_in[1];
    const float* gt   = (const float*)d_in[2];
    const float* diff = (const float*)d_in[3];
    float* out = (float*)d_out;

    cost_kernel <<<dim3(SB, NTILE, 2), TILE>>>(fir, sec, gt);
    final_kernel<<<1, 1024>>>(fir, sec, gt, diff, out);
}

// round 8
// speedup vs baseline: 4.4689x; 1.5730x over previous
#include <cuda_runtime.h>
#include <math.h>
#include <limits.h>

#define S_STAGES 3
#define BATCH    32
#define NPRIOR   2000
#define LANES    4
#define DFEAT    78          // 2 + 4 + 72
#define NOFF     72
#define SB       96
#define IMG_W_F  800.0f
#define IMG_W1_F 799.0f
#define TILE     128
#define NTILE    16          // 15 full tiles + one of 80
#define RP2      44          // buffer row stride (floats)
#define NCAND    (NTILE * 4) // 64 candidates per column
#define NMATCH   (2 * SB * LANES)   // 768
#define NTASK    (2 * SB)           // 192
#define FIXSCALE 1099511627776.0f   // 2^40

// Scratch (device globals — no allocation allowed)
// g_cls_acc is zero at load; final_kernel re-zeroes after consuming (replay-safe).
__device__ unsigned long long g_cls_acc[2 * NPRIOR];
__device__ float g_cv[NTASK * LANES * NCAND];
__device__ int   g_ci[NTASK * LANES * NCAND];
__device__ int   g_rows[NMATCH];
__device__ float g_reg [NMATCH];
__device__ float g_iou [NMATCH];
__device__ float g_corr[NMATCH];

__device__ __forceinline__ void cp_async8(unsigned s, const void* g) {
    asm volatile("cp.async.ca.shared.global [%0], [%1], 8;\n" :: "r"(s), "l"(g));
}
__device__ __forceinline__ void cp_commit() {
    asm volatile("cp.async.commit_group;\n" ::: "memory");
}
__device__ __forceinline__ void cp_wait0() {
    asm volatile("cp.async.wait_group 0;\n" ::: "memory");
}

// ---------------------------------------------------------------------------
// Kernel 1: two-phase staged cost + candidate top-4 + fixed-point cls RED.
// grid (96, NTILE, 2), 128 threads.
// ---------------------------------------------------------------------------
__global__ __launch_bounds__(TILE) void cost_kernel(
    const float* __restrict__ predA,
    const float* __restrict__ predB,
    const float* __restrict__ gt)
{
    const int sb     = blockIdx.x;
    const int tile   = blockIdx.y;
    const int branch = blockIdx.z;
    const int n0     = tile * TILE;
    const int T      = (n0 + TILE <= NPRIOR) ? TILE : (NPRIOR - n0);
    const float* __restrict__ pred = branch ? predB : predA;
    const int b = sb % BATCH;
    const char* gbase = (const char*)(pred + ((size_t)sb * NPRIOR + n0) * DFEAT);
    const size_t bs = (size_t)branch * SB + sb;

    __shared__ __align__(16) float sh_buf[TILE * RP2];     // 22528 B
    __shared__ __align__(16) float sh_goff[LANES][80];
    __shared__ float sh_geo[LANES][4];
    __shared__ float sh_c[LANES][TILE];

    const int tid  = threadIdx.x;
    const int warp = tid >> 5, lane = tid & 31;
    const unsigned FULL = 0xffffffffu;
    const unsigned sp = (unsigned)__cvta_generic_to_shared(sh_buf);

    // ---- stage phase A: dims 0..39 (20 x 8B chunks per row)
    {
        int row = tid / 20, c2 = tid - row * 20, f = tid;
        const int total = T * 20;
        while (f < total) {
            cp_async8(sp + (unsigned)(row * (RP2 * 4) + c2 * 8),
                      gbase + (size_t)row * 312 + c2 * 8);
            f += 128; row += 6; c2 += 8;
            if (c2 >= 20) { c2 -= 20; row += 1; }
        }
        cp_commit();
    }

    // gt tables (overlap with cp.async)
    for (int i = tid; i < LANES * 80; i += TILE) {
        int l = i / 80, d = i % 80;
        float v = 0.0f;
        if (d >= 6 && d < DFEAT)
            v = gt[((size_t)b * LANES + l) * DFEAT + d] * (1.0f / IMG_W1_F);
        sh_goff[l][d] = v;
    }
    if (tid < 16)
        sh_geo[tid >> 2][tid & 3] =
            gt[((size_t)b * LANES + (tid >> 2)) * DFEAT + 2 + (tid & 3)];

    cp_wait0();
    __syncthreads();

    // ---- compute phase A
    float cg[LANES], o[LANES];
    float score = 0.0f;
    if (tid < T) {
        const float* rp = sh_buf + tid * RP2;
        float4 p0 = *reinterpret_cast<const float4*>(rp);
        float4 p1 = *reinterpret_cast<const float4*>(rp + 4);
        #pragma unroll
        for (int l = 0; l < LANES; l++) {
            cg[l] = fabsf(p0.z - sh_geo[l][0]) + fabsf(p0.w - sh_geo[l][1])
                  + fabsf(p1.x - sh_geo[l][2]) + fabsf(p1.y - sh_geo[l][3]);
            o[l]  = fabsf(p1.z - sh_goff[l][6]) + fabsf(p1.w - sh_goff[l][7]);
        }
        #pragma unroll
        for (int c = 2; c < 10; c++) {
            float4 pv = *reinterpret_cast<const float4*>(rp + 4 * c);
            #pragma unroll
            for (int l = 0; l < LANES; l++) {
                float4 gv = *reinterpret_cast<const float4*>(&sh_goff[l][4 * c]);
                o[l] += fabsf(pv.x - gv.x) + fabsf(pv.y - gv.y)
                      + fabsf(pv.z - gv.z) + fabsf(pv.w - gv.w);
            }
        }
        float x0 = p0.x, x1 = p0.y;
        float m  = fmaxf(x0, x1);
        float e0 = expf(x0 - m), e1 = expf(x1 - m);
        float denom = e0 + e1;
        score = e1 / denom;
        float lse = m + logf(denom);
        float om0 = 1.0f - e0 / denom;
        float cneg = -0.1f * om0 * om0 * (x0 - lse);
        atomicAdd(&g_cls_acc[branch * NPRIOR + n0 + tid],
                  (unsigned long long)(long long)__float2ll_rn(cneg * FIXSCALE));
    }
    __syncthreads();

    // ---- stage phase B: dims 40..77
    {
        int row = tid / 19, c2 = tid - row * 19, f = tid;
        const int total = T * 19;
        while (f < total) {
            cp_async8(sp + (unsigned)(row * (RP2 * 4) + c2 * 8),
                      gbase + (size_t)row * 312 + 160 + c2 * 8);
            f += 128; row += 6; c2 += 14;
            if (c2 >= 19) { c2 -= 19; row += 1; }
        }
        cp_commit();
    }
    if (tid < T) {
        sh_buf[tid * RP2 + 38] = 0.0f;
        sh_buf[tid * RP2 + 39] = 0.0f;
    }
    cp_wait0();
    __syncthreads();

    // ---- compute phase B
    if (tid < T) {
        const float* rp = sh_buf + tid * RP2;
        #pragma unroll
        for (int c = 0; c < 10; c++) {
            float4 pv = *reinterpret_cast<const float4*>(rp + 4 * c);
            #pragma unroll
            for (int l = 0; l < LANES; l++) {
                float4 gv = *reinterpret_cast<const float4*>(&sh_goff[l][40 + 4 * c]);
                o[l] += fabsf(pv.x - gv.x) + fabsf(pv.y - gv.y)
                      + fabsf(pv.z - gv.z) + fabsf(pv.w - gv.w);
            }
        }
        #pragma unroll
        for (int l = 0; l < LANES; l++)
            sh_c[l][tid] = cg[l] + o[l] * (1.0f / 72.0f) - score;
    } else {
        #pragma unroll
        for (int l = 0; l < LANES; l++) sh_c[l][tid] = INFINITY;
    }
    __syncthreads();

    // ---- warp w: top-4 of column w within tile
    {
        const int w = warp;
        const size_t base = ((bs * LANES + w) * NTILE + tile) * 4;
        #pragma unroll
        for (int pass = 0; pass < 4; pass++) {
            float v = INFINITY; int li = INT_MAX;
            #pragma unroll
            for (int j0 = 0; j0 < TILE; j0 += 32) {
                int j = j0 + lane;
                float cc = sh_c[w][j];
                if (cc < v || (cc == v && j < li)) { v = cc; li = j; }
            }
            #pragma unroll
            for (int off = 16; off; off >>= 1) {
                float v2 = __shfl_xor_sync(FULL, v, off);
                int   i2 = __shfl_xor_sync(FULL, li, off);
                if (v2 < v || (v2 == v && i2 < li)) { v = v2; li = i2; }
            }
            if (lane == 0) {
                g_cv[base + pass] = v;
                g_ci[base + pass] = n0 + li;
                sh_c[w][li] = INFINITY;
            }
            __syncwarp(FULL);
        }
    }
}

// ---------------------------------------------------------------------------
// Kernel 2: per-task greedy merge + reg/iou/corr. grid 192, 128 threads.
// ---------------------------------------------------------------------------
__global__ __launch_bounds__(128) void match_kernel(
    const float* __restrict__ predA,
    const float* __restrict__ predB,
    const float* __restrict__ gt)
{
    const int task   = blockIdx.x;             // 0..191
    const int branch = task / SB;
    const int sb     = task % SB;
    const int b      = sb % BATCH;

    __shared__ int rows_sh[LANES];

    const int tid  = threadIdx.x;
    const int warp = tid >> 5, lane = tid & 31;
    const unsigned FULL = 0xffffffffu;

    // warp 0: greedy merge over candidates
    if (warp == 0) {
        const size_t base = (size_t)task * LANES * NCAND;
        float cv[LANES][2]; int ci[LANES][2];
        #pragma unroll
        for (int col = 0; col < LANES; col++) {
            cv[col][0] = g_cv[base + col * NCAND + lane];
            cv[col][1] = g_cv[base + col * NCAND + 32 + lane];
            ci[col][0] = g_ci[base + col * NCAND + lane];
            ci[col][1] = g_ci[base + col * NCAND + 32 + lane];
        }
        int u0 = -1, u1 = -1, u2 = -1;
        #pragma unroll
        for (int col = 0; col < LANES; col++) {
            float v = INFINITY; int li = INT_MAX;
            #pragma unroll
            for (int k = 0; k < 2; k++) {
                int   i2 = ci[col][k];
                float v2 = cv[col][k];
                bool excl = (i2 == u0) | (i2 == u1) | (i2 == u2);
                if (!excl && (v2 < v || (v2 == v && i2 < li))) { v = v2; li = i2; }
            }
            #pragma unroll
            for (int off = 16; off; off >>= 1) {
                float v2 = __shfl_xor_sync(FULL, v, off);
                int   i2 = __shfl_xor_sync(FULL, li, off);
                if (v2 < v || (v2 == v && i2 < li)) { v = v2; li = i2; }
            }
            if (lane == 0) { rows_sh[col] = li; g_rows[task * LANES + col] = li; }
            if (col == 0) u0 = li; else if (col == 1) u1 = li; else if (col == 2) u2 = li;
        }
    }
    __syncthreads();

    // warp l: reg + iou + focal correction for matched lane l
    {
        const int l = warp;
        const int r = rows_sh[l];
        const int mm = task * LANES + l;
        const float* p  = (branch ? predB : predA)
                          + ((size_t)sb * NPRIOR + r) * DFEAT;
        const float* tg = gt + ((size_t)b * LANES + l) * DFEAT;

        float ovrS = 0.0f, uniS = 0.0f;
        #pragma unroll
        for (int kb = 0; kb < 3; kb++) {
            int k = kb * 32 + lane;
            if (k < NOFF) {
                float rp = p[6 + k] * IMG_W1_F;
                float rt = tg[6 + k];
                bool invalid = (rt < 0.0f) || (rt >= IMG_W_F);
                float mn = fminf(rp, rt), mx = fmaxf(rp, rt);
                if (!invalid) {
                    ovrS += (mn - mx + 30.0f);
                    uniS += (mx - mn + 30.0f);
                }
            }
        }
        #pragma unroll
        for (int off = 16; off; off >>= 1) {
            ovrS += __shfl_xor_sync(FULL, ovrS, off);
            uniS += __shfl_xor_sync(FULL, uniS, off);
        }
        if (lane == 0) {
            float iou = ovrS / (uniS + 1e-9f);
            g_iou[mm] = (1.0f - iou) * 0.25f;
            const float sc[4] = {71.0f, IMG_W1_F, 180.0f, 71.0f};
            float ssum = 0.0f;
            #pragma unroll
            for (int j = 0; j < 4; j++) {
                float d  = (p[2 + j] - tg[2 + j]) * sc[j];
                float ad = fabsf(d);
                ssum += (ad < 1.0f) ? 0.5f * d * d : ad - 0.5f;
            }
            g_reg[mm] = ssum * 0.0625f;   // mean over 4, /L

            float x0 = p[0], x1 = p[1];
            float m2  = fmaxf(x0, x1);
            float e0 = expf(x0 - m2), e1 = expf(x1 - m2);
            float denom = e0 + e1;
            float lse = m2 + logf(denom);
            float om0 = 1.0f - e0 / denom, om1 = 1.0f - e1 / denom;
            float cneg = -0.1f * om0 * om0 * (x0 - lse);
            float cpos = -0.9f * om1 * om1 * (x1 - lse);
            g_corr[mm] = (cpos - cneg) * (2.0f / 96.0f);
        }
    }
}

// ---------------------------------------------------------------------------
// Kernel 3: inst build + corrections + dual-rank radix median + weighted sum.
// Single block, 1024 threads.
// ---------------------------------------------------------------------------
__global__ __launch_bounds__(1024) void final_kernel(
    const float* __restrict__ diff,
    float* __restrict__ out)
{
    __shared__ float instA[NPRIOR];
    __shared__ float instB[NPRIOR];
    __shared__ unsigned ukey[NPRIOR];
    __shared__ int   hist[2][256];
    __shared__ float red[1024];
    __shared__ int   s_bin[2], s_k[2];

    const int tid = threadIdx.x;
    const int warp = tid >> 5, lane = tid & 31;
    const unsigned FULL = 0xffffffffu;

    // inst from fixed-point cls accumulators; restore zeros (replay-safe)
    const float CLS_K = (float)(2.0 / 96.0 / 1099511627776.0);
    for (int n = tid; n < NPRIOR; n += 1024) {
        long long a0 = (long long)g_cls_acc[n];
        long long b0 = (long long)g_cls_acc[NPRIOR + n];
        instA[n] = (float)a0 * CLS_K;
        instB[n] = (float)b0 * CLS_K;
        g_cls_acc[n] = 0ull;
        g_cls_acc[NPRIOR + n] = 0ull;
    }
    __syncthreads();

    // matched-row focal corrections
    if (tid < NMATCH) {
        const int branch = tid / (SB * LANES);
        const int r = g_rows[tid];
        atomicAdd(branch == 0 ? &instA[r] : &instB[r], g_corr[tid]);
    }
    // reg/iou sums + scatter at rows[-1,-1]
    if (tid >= 1016) {
        const int t = tid - 1016;
        const int branch = t >> 2, l = t & 3;
        float rs = 0.0f, is = 0.0f;
        #pragma unroll 8
        for (int i = 0; i < SB; i++) {
            rs += g_reg[(branch * SB + i) * LANES + l];
            is += g_iou[(branch * SB + i) * LANES + l];
        }
        float add = rs * (0.5f / 96.0f) + is * (2.0f / 96.0f);
        int r = g_rows[(branch * SB + (SB - 1)) * LANES + l];
        atomicAdd(branch == 0 ? &instA[r] : &instB[r], add);
    }
    __syncthreads();

    // median via dual-rank radix select
    for (int n = tid; n < NPRIOR; n += 1024) {
        float f = instA[n] - instB[n];
        unsigned x = __float_as_uint(f);
        ukey[n] = (x & 0x80000000u) ? ~x : (x | 0x80000000u);
    }
    __syncthreads();

    unsigned prefix[2] = {0u, 0u};
    unsigned mask = 0u;
    int kk[2] = {999, 1000};
    for (int shift = 24; shift >= 0; shift -= 8) {
        if (tid < 512) hist[tid >> 8][tid & 255] = 0;
        __syncthreads();
        for (int n = tid; n < NPRIOR; n += 1024) {
            unsigned u = ukey[n];
            unsigned bin = (u >> shift) & 255u;
            unsigned hi = u & mask;
            if (hi == prefix[0]) atomicAdd(&hist[0][bin], 1);
            if (hi == prefix[1]) atomicAdd(&hist[1][bin], 1);
        }
        __syncthreads();
        if (tid < 64) {
            const int trk = warp;
            int kt = kk[trk];
            int cnt[8]; int local = 0;
            #pragma unroll
            for (int k2 = 0; k2 < 8; k2++) { cnt[k2] = hist[trk][lane * 8 + k2]; local += cnt[k2]; }
            int pre = local;
            #pragma unroll
            for (int off = 1; off < 32; off <<= 1) {
                int t2 = __shfl_up_sync(FULL, pre, off);
                if (lane >= off) pre += t2;
            }
            int run = pre - local;
            int foundk = -1, myrun = 0;
            #pragma unroll
            for (int k2 = 0; k2 < 8; k2++) {
                if (foundk < 0 && kt >= run && kt < run + cnt[k2]) { foundk = k2; myrun = run; }
                run += cnt[k2];
            }
            unsigned bm = __ballot_sync(FULL, foundk >= 0);
            int src = __ffs(bm) - 1;
            if (lane == src) { s_bin[trk] = lane * 8 + foundk; s_k[trk] = kt - myrun; }
        }
        __syncthreads();
        prefix[0] |= ((unsigned)s_bin[0]) << shift;
        prefix[1] |= ((unsigned)s_bin[1]) << shift;
        mask |= 0xFFu << shift;
        kk[0] = s_k[0]; kk[1] = s_k[1];
        __syncthreads();
    }
    float m0 = (prefix[0] & 0x80000000u) ? __uint_as_float(prefix[0] ^ 0x80000000u)
                                         : __uint_as_float(~prefix[0]);
    float m1 = (prefix[1] & 0x80000000u) ? __uint_as_float(prefix[1] ^ 0x80000000u)
                                         : __uint_as_float(~prefix[1]);
    float delta = 0.5f * (m0 + m1);

    // final weighted sum
    float acc = 0.0f;
    for (int n = tid; n < NPRIOR; n += 1024) {
        float dm = (diff[n] + diff[NPRIOR + n] + diff[2 * NPRIOR + n]) * (1.0f / 3.0f);
        acc += (1.0f - dm) * (instA[n] - 0.5f * delta)
             + dm          * (instB[n] + 0.5f * delta);
    }
    red[tid] = acc;
    __syncthreads();
    for (int off = 512; off; off >>= 1) {
        if (tid < off) red[tid] += red[tid + off];
        __syncthreads();
    }
    if (tid == 0) out[0] = red[0];
}

// ---------------------------------------------------------------------------
extern "C" void kernel_launch(void* const* d_in, const int* in_sizes, int n_in,
                              void* d_out, int out_size)
{
    const float* fir  = (const float*)d_in[0];
    const float* sec  = (const float*)d_in[1];
    const float* gt   = (const float*)d_in[2];
    const float* diff = (const float*)d_in[3];
    float* out = (float*)d_out;

    cost_kernel <<<dim3(SB, NTILE, 2), TILE>>>(fir, sec, gt);
    match_kernel<<<NTASK, 128>>>(fir, sec, gt);
    final_kernel<<<1, 1024>>>(diff, out);
}